// round 15
// baseline (speedup 1.0000x reference)
#include <cuda_runtime.h>
#include <cuda_fp16.h>
#include <cstdint>

#define NN 50000
#define EE 800000
#define NPB 128   // nodes per block for the GEMM kernels
#define HS_H 72   // h-tile smem stride in halves (144 B: conflict-free ldmatrix)
#define WT_S 72   // transposed-W smem stride in halves

// Scratch (allocation-free rule: __device__ globals)
__device__ __half g_feat[NN * 64];   // fp16 feat: 128 B / node record
__device__ float  g_el[NN * 4];
__device__ float  g_er[NN * 4];
__device__ int    g_idx64;           // 1 if src/dst are int64, 0 if int32
__device__ int    g_cnt[NN];         // per-dst degree
__device__ int    g_off[NN + 1];     // CSR offsets
__device__ int    g_cur[NN];         // scatter cursors
__device__ int    g_ssrc[EE];        // src ids grouped by dst

__device__ __forceinline__ uint32_t smem_u32(const void* p)
{
    return (uint32_t)__cvta_generic_to_shared(p);
}

__device__ __forceinline__ int load_idx(const void* p, int e)
{
    if (g_idx64) return (int)__ldg(&((const long long*)p)[e]);
    return __ldg(&((const int*)p)[e]);
}

// ---------------------------------------------------------------------------
// zero_all: out = 0, g_cnt = 0, and probe index dtype (node ids < 2^31 =>
// int64 encoding has zero high words at odd 32-bit slots).
// ---------------------------------------------------------------------------
__global__ __launch_bounds__(256)
void zero_all(float4* __restrict__ out4, const unsigned* __restrict__ src_words)
{
    const int i = blockIdx.x * 256 + threadIdx.x;
    if (i == 0) {
        g_idx64 = (src_words[1] == 0u && src_words[3] == 0u &&
                   src_words[5] == 0u && src_words[7] == 0u) ? 1 : 0;
    }
    if (i < NN * 16) {
        out4[i] = make_float4(0.f, 0.f, 0.f, 0.f);
    } else {
        const int j = i - NN * 16;
        if (j < NN / 4)
            reinterpret_cast<int4*>(g_cnt)[j] = make_int4(0, 0, 0, 0);
    }
}

// ---------------------------------------------------------------------------
// hist: g_cnt[dst[e]]++   (validated R11/R13)
// ---------------------------------------------------------------------------
__global__ __launch_bounds__(256)
void hist_kernel(const void* __restrict__ dst_raw)
{
    const int e = blockIdx.x * 256 + threadIdx.x;
    if (e < EE) atomicAdd(&g_cnt[load_idx(dst_raw, e)], 1);
}

// ---------------------------------------------------------------------------
// scan: exclusive prefix sum of g_cnt -> g_off (and g_cur). Single block.
// (validated R11/R13)
// ---------------------------------------------------------------------------
__global__ __launch_bounds__(1024)
void scan_kernel()
{
    __shared__ int ssum[1024];
    const int t   = threadIdx.x;
    const int PER = (NN + 1023) / 1024;   // 49
    const int base = t * PER;

    int sum = 0;
    for (int i = 0; i < PER; i++) {
        const int idx = base + i;
        if (idx < NN) sum += g_cnt[idx];
    }
    ssum[t] = sum;
    __syncthreads();

    int val = sum;
    for (int o = 1; o < 1024; o <<= 1) {
        const int v = (t >= o) ? ssum[t - o] : 0;
        __syncthreads();
        val += v;
        ssum[t] = val;
        __syncthreads();
    }
    const int excl = val - sum;            // exclusive prefix for this thread
    if (t == 1023) g_off[NN] = val;        // grand total (= EE)

    int run = excl;
    for (int i = 0; i < PER; i++) {
        const int idx = base + i;
        if (idx < NN) {
            g_off[idx] = run;
            g_cur[idx] = run;
            run += g_cnt[idx];
        }
    }
}

// ---------------------------------------------------------------------------
// scatter: sorted-by-dst src list via per-dst cursors. (validated R11/R13)
// ---------------------------------------------------------------------------
__global__ __launch_bounds__(256)
void scatter_kernel(const void* __restrict__ src_raw,
                    const void* __restrict__ dst_raw)
{
    const int e = blockIdx.x * 256 + threadIdx.x;
    if (e < EE) {
        const int d = load_idx(dst_raw, e);
        const int s = load_idx(src_raw, e);
        const int pos = atomicAdd(&g_cur[d], 1);
        g_ssrc[pos] = s;
    }
}

// ---------------------------------------------------------------------------
// feat kernel (fp16 tensor cores, ldmatrix-fed): feat = h@W_fc (stored fp16),
// el/er head-dots from the fp32 accumulators. 4 warps, 2x8 m16n8k16 tiles.
// ---------------------------------------------------------------------------
__global__ __launch_bounds__(128)
void feat_kernel(const float* __restrict__ h,
                 const float* __restrict__ Wfc,
                 const float* __restrict__ al,
                 const float* __restrict__ ar)
{
    extern __shared__ float smem[];
    __half* hs   = reinterpret_cast<__half*>(smem);           // [128][HS_H]
    __half* Wt   = hs + 128 * HS_H;                           // [64][WT_S]
    float*  al_s = reinterpret_cast<float*>(Wt + 64 * WT_S);  // 64
    float*  ar_s = al_s + 64;                                 // 64

    const int t   = threadIdx.x;
    const int nb0 = blockIdx.x * NPB;

    if (t < 64)       al_s[t]      = al[t];
    else if (t < 128) ar_s[t - 64] = ar[t - 64];

    #pragma unroll
    for (int i = 0; i < 32; i++) {
        const int idx = i * 128 + t;
        const int k = idx >> 6, n = idx & 63;
        Wt[n * WT_S + k] = __float2half(Wfc[idx]);
    }

    {
        const int n = nb0 + t;
        #pragma unroll
        for (int k4 = 0; k4 < 16; k4++) {
            float4 v = make_float4(0.f, 0.f, 0.f, 0.f);
            if (n < NN) v = reinterpret_cast<const float4*>(h)[n * 16 + k4];
            *reinterpret_cast<__half2*>(&hs[t * HS_H + k4 * 4 + 0]) =
                __floats2half2_rn(v.x, v.y);
            *reinterpret_cast<__half2*>(&hs[t * HS_H + k4 * 4 + 2]) =
                __floats2half2_rn(v.z, v.w);
        }
    }
    __syncthreads();

    const int w   = t >> 5;
    const int ln  = t & 31;
    const int gid = ln >> 2;
    const int q   = ln & 3;
    const int rbase = w * 32;

    const int arow_l = ln & 15;
    const int akoff  = (ln >> 4) * 8;
    const int brow_l = ln & 7;
    const int bj     = ln >> 3;
    const int bkoff  = (bj & 1) * 8;
    const int bnsel  = bj >> 1;

    const uint32_t hs_base = smem_u32(hs);
    const uint32_t wt_base = smem_u32(Wt);

    float acc[2][8][4];
    #pragma unroll
    for (int m = 0; m < 2; m++)
        #pragma unroll
        for (int nt = 0; nt < 8; nt++)
            #pragma unroll
            for (int c = 0; c < 4; c++) acc[m][nt][c] = 0.f;

    #pragma unroll
    for (int ks = 0; ks < 4; ks++) {
        const int k0 = ks * 16;
        uint32_t a[2][4];
        #pragma unroll
        for (int m = 0; m < 2; m++) {
            const uint32_t addr = hs_base +
                ((rbase + m * 16 + arow_l) * HS_H + k0 + akoff) * 2;
            asm volatile(
                "ldmatrix.sync.aligned.m8n8.x4.shared.b16 {%0,%1,%2,%3}, [%4];"
                : "=r"(a[m][0]), "=r"(a[m][1]), "=r"(a[m][2]), "=r"(a[m][3])
                : "r"(addr));
        }
        #pragma unroll
        for (int np = 0; np < 4; np++) {
            uint32_t b[4];
            const int nrow = (2 * np + bnsel) * 8 + brow_l;
            const uint32_t baddr = wt_base + (nrow * WT_S + k0 + bkoff) * 2;
            asm volatile(
                "ldmatrix.sync.aligned.m8n8.x4.shared.b16 {%0,%1,%2,%3}, [%4];"
                : "=r"(b[0]), "=r"(b[1]), "=r"(b[2]), "=r"(b[3])
                : "r"(baddr));
            #pragma unroll
            for (int hf = 0; hf < 2; hf++) {
                const int nt = 2 * np + hf;
                #pragma unroll
                for (int m = 0; m < 2; m++) {
                    asm volatile(
                        "mma.sync.aligned.m16n8k16.row.col.f32.f16.f16.f32 "
                        "{%0,%1,%2,%3},{%4,%5,%6,%7},{%8,%9},{%0,%1,%2,%3};"
                        : "+f"(acc[m][nt][0]), "+f"(acc[m][nt][1]),
                          "+f"(acc[m][nt][2]), "+f"(acc[m][nt][3])
                        : "r"(a[m][0]), "r"(a[m][1]), "r"(a[m][2]), "r"(a[m][3]),
                          "r"(b[hf * 2 + 0]), "r"(b[hf * 2 + 1]));
                }
            }
        }
    }

    #pragma unroll
    for (int m = 0; m < 2; m++) {
        #pragma unroll
        for (int half = 0; half < 2; half++) {
            const int n = nb0 + rbase + m * 16 + gid + half * 8;
            float e_l[4] = {0.f, 0.f, 0.f, 0.f};
            float e_r[4] = {0.f, 0.f, 0.f, 0.f};
            #pragma unroll
            for (int nt = 0; nt < 8; nt++) {
                const int hH  = nt >> 1;
                const int c16 = (nt & 1) * 8 + 2 * q;
                const float v0 = acc[m][nt][half * 2 + 0];
                const float v1 = acc[m][nt][half * 2 + 1];
                e_l[hH] += v0 * al_s[hH * 16 + c16] + v1 * al_s[hH * 16 + c16 + 1];
                e_r[hH] += v0 * ar_s[hH * 16 + c16] + v1 * ar_s[hH * 16 + c16 + 1];
            }
            #pragma unroll
            for (int hH = 0; hH < 4; hH++) {
                e_l[hH] += __shfl_xor_sync(0xFFFFFFFFu, e_l[hH], 1);
                e_l[hH] += __shfl_xor_sync(0xFFFFFFFFu, e_l[hH], 2);
                e_r[hH] += __shfl_xor_sync(0xFFFFFFFFu, e_r[hH], 1);
                e_r[hH] += __shfl_xor_sync(0xFFFFFFFFu, e_r[hH], 2);
            }
            if (n < NN) {
                #pragma unroll
                for (int nt = 0; nt < 8; nt++) {
                    const __half2 hv = __floats2half2_rn(acc[m][nt][half * 2 + 0],
                                                         acc[m][nt][half * 2 + 1]);
                    *reinterpret_cast<__half2*>(&g_feat[n * 64 + nt * 8 + 2 * q]) = hv;
                }
                const float ev = (q == 0) ? e_l[0] : (q == 1) ? e_l[1]
                               : (q == 2) ? e_l[2] : e_l[3];
                const float rv = (q == 0) ? e_r[0] : (q == 1) ? e_r[1]
                               : (q == 2) ? e_r[2] : e_r[3];
                g_el[n * 4 + q] = ev;
                g_er[n * 4 + q] = rv;
            }
        }
    }
}

// ---------------------------------------------------------------------------
// resval kernel (fp32 FFMA, off critical path): out += h @ W_res via RED.
// ---------------------------------------------------------------------------
__global__ __launch_bounds__(128, 4)
void resval_kernel(const float* __restrict__ h,
                   const float* __restrict__ Wres,
                   float* __restrict__ out)
{
    extern __shared__ float smem[];
    float* sW = smem;
    float* sT = smem + 4096;

    const int t   = threadIdx.x;
    const int nb0 = blockIdx.x * NPB;

    #pragma unroll
    for (int i = 0; i < 32; i++) sW[i * 128 + t] = Wres[i * 128 + t];

    {
        const int n = nb0 + t;
        #pragma unroll
        for (int k4 = 0; k4 < 16; k4++) {
            float4 v = make_float4(0.f, 0.f, 0.f, 0.f);
            if (n < NN) v = reinterpret_cast<const float4*>(h)[n * 16 + k4];
            sT[(k4 * 4 + 0) * 128 + t] = v.x;
            sT[(k4 * 4 + 1) * 128 + t] = v.y;
            sT[(k4 * 4 + 2) * 128 + t] = v.z;
            sT[(k4 * 4 + 3) * 128 + t] = v.w;
        }
    }
    __syncthreads();

    const int g    = t >> 2;
    const int head = t & 3;

    const float4* sT4 = reinterpret_cast<const float4*>(sT);
    const float4* sW4 = reinterpret_cast<const float4*>(sW);

    float acc[4][16];
    #pragma unroll
    for (int i = 0; i < 4; i++)
        #pragma unroll
        for (int j = 0; j < 16; j++) acc[i][j] = 0.f;

    #pragma unroll 4
    for (int k = 0; k < 64; k++) {
        float4 hv = sT4[k * 32 + g];
        float hvv[4] = {hv.x, hv.y, hv.z, hv.w};
        #pragma unroll
        for (int jq = 0; jq < 4; jq++) {
            float4 wv = sW4[k * 16 + head * 4 + jq];
            #pragma unroll
            for (int i = 0; i < 4; i++) {
                acc[i][jq * 4 + 0] += hvv[i] * wv.x;
                acc[i][jq * 4 + 1] += hvv[i] * wv.y;
                acc[i][jq * 4 + 2] += hvv[i] * wv.z;
                acc[i][jq * 4 + 3] += hvv[i] * wv.w;
            }
        }
    }

    #pragma unroll
    for (int i = 0; i < 4; i++) {
        const int n = nb0 + g * 4 + i;
        if (n < NN) {
            float* op = &out[n * 64 + head * 16];
            #pragma unroll
            for (int jq = 0; jq < 4; jq++) {
                asm volatile("red.global.add.v4.f32 [%0], {%1,%2,%3,%4};"
                             :: "l"(op + jq * 4),
                                "f"(acc[i][jq * 4 + 0]), "f"(acc[i][jq * 4 + 1]),
                                "f"(acc[i][jq * 4 + 2]), "f"(acc[i][jq * 4 + 3])
                             : "memory");
            }
        }
    }
}

// ---------------------------------------------------------------------------
// gather kernel v4: ONE WARP PER NODE. Lane = (half, sub): half = edge
// parity (2 edges in flight), sub in [0,16) owns dims [sub*4, sub*4+4).
// Uniform trip count per warp (no cross-node divergence). In-lane softmax
// from one broadcast el float4; feat read = 16 lanes x 8 B contiguous.
// End: shfl_xor(16) merges parities; half==0 lanes issue one RED each
// (8 sectors per NODE, ~0.5/edge vs 8/edge in the flat edge kernel).
// ---------------------------------------------------------------------------
__global__ __launch_bounds__(256)
void gather_kernel(float* __restrict__ out)
{
    const int node = (blockIdx.x * 256 + threadIdx.x) >> 5;
    if (node >= NN) return;                 // whole warp exits together
    const int lane = threadIdx.x & 31;
    const int half = lane >> 4;
    const int sub  = lane & 15;
    const int hsel = sub >> 2;              // head owning this lane's dims

    const int start = __ldg(&g_off[node]);
    const int end   = __ldg(&g_off[node + 1]);
    if (start >= end) return;               // uniform across the warp

    const float4 erv = __ldg(reinterpret_cast<const float4*>(g_er + node * 4));

    float a0 = 0.f, a1 = 0.f, a2 = 0.f, a3 = 0.f;

    for (int i = start + half; i < end; i += 2) {
        const int s = __ldg(&g_ssrc[i]);
        const float4 elv = __ldg(reinterpret_cast<const float4*>(g_el + s * 4));
        const uint2  u   = __ldg(reinterpret_cast<const uint2*>(g_feat + s * 64 + sub * 4));

        float x0 = elv.x + erv.x; x0 = (x0 > 0.f) ? x0 : 0.2f * x0;
        float x1 = elv.y + erv.y; x1 = (x1 > 0.f) ? x1 : 0.2f * x1;
        float x2 = elv.z + erv.z; x2 = (x2 > 0.f) ? x2 : 0.2f * x2;
        float x3 = elv.w + erv.w; x3 = (x3 > 0.f) ? x3 : 0.2f * x3;
        const float mx = fmaxf(fmaxf(x0, x1), fmaxf(x2, x3));
        const float p0 = __expf(x0 - mx), p1 = __expf(x1 - mx);
        const float p2 = __expf(x2 - mx), p3 = __expf(x3 - mx);
        const float inv = 1.0f / (p0 + p1 + p2 + p3);
        const float ph = (hsel == 0) ? p0 : (hsel == 1) ? p1
                       : (hsel == 2) ? p2 : p3;
        const float a = ph * inv;

        const float2 f0 = __half22float2(*reinterpret_cast<const __half2*>(&u.x));
        const float2 f1 = __half22float2(*reinterpret_cast<const __half2*>(&u.y));
        a0 += f0.x * a;
        a1 += f0.y * a;
        a2 += f1.x * a;
        a3 += f1.y * a;
    }

    // Merge the two edge-parity streams (full-warp sync shuffles).
    a0 += __shfl_xor_sync(0xFFFFFFFFu, a0, 16);
    a1 += __shfl_xor_sync(0xFFFFFFFFu, a1, 16);
    a2 += __shfl_xor_sync(0xFFFFFFFFu, a2, 16);
    a3 += __shfl_xor_sync(0xFFFFFFFFu, a3, 16);

    if (half == 0) {
        float* o = out + node * 64 + sub * 4;
        asm volatile("red.global.add.v4.f32 [%0], {%1,%2,%3,%4};"
                     :: "l"(o), "f"(a0), "f"(a1), "f"(a2), "f"(a3)
                     : "memory");
    }
}

// ---------------------------------------------------------------------------
// Schedule:
//   s2 : zero(out+cnt,probe) → hist → scan → scatter ──────[evCSR]
//   s3 : [wait zero] resval (RED into out) ────────────────[evResv]
//   s1 : feat(mma) ───────────► [wait evCSR] gather ───► [wait evResv]
// ---------------------------------------------------------------------------
extern "C" void kernel_launch(void* const* d_in, const int* in_sizes, int n_in,
                              void* d_out, int out_size)
{
    const float* h    = (const float*)d_in[0];
    const void*  src  = d_in[1];
    const void*  dst  = d_in[2];
    const float* Wfc  = (const float*)d_in[3];
    const float* al   = (const float*)d_in[4];
    const float* ar   = (const float*)d_in[5];
    const float* Wres = (const float*)d_in[6];
    float* out = (float*)d_out;

    const int feat_smem   = (128 * HS_H + 64 * WT_S) * 2 + 128 * (int)sizeof(float);
    const int resval_smem = (4096 + 64 * NPB) * (int)sizeof(float);

    // One-time host-side resources (no device memory involved).
    static bool         s_init = false;
    static cudaStream_t s2, s3;
    static cudaEvent_t  evFork, evZero, evCSR, evResv;
    if (!s_init) {
        cudaStreamCreateWithFlags(&s2, cudaStreamNonBlocking);
        cudaStreamCreateWithFlags(&s3, cudaStreamNonBlocking);
        cudaEventCreateWithFlags(&evFork, cudaEventDisableTiming);
        cudaEventCreateWithFlags(&evZero, cudaEventDisableTiming);
        cudaEventCreateWithFlags(&evCSR,  cudaEventDisableTiming);
        cudaEventCreateWithFlags(&evResv, cudaEventDisableTiming);
        cudaFuncSetAttribute(feat_kernel,
                             cudaFuncAttributeMaxDynamicSharedMemorySize, feat_smem);
        cudaFuncSetAttribute(resval_kernel,
                             cudaFuncAttributeMaxDynamicSharedMemorySize, resval_smem);
        s_init = true;
    }

    const int node_blocks = (NN + NPB - 1) / NPB;               // 391

    // Fork s2: zero + CSR build.
    cudaEventRecord(evFork, 0);
    cudaStreamWaitEvent(s2, evFork, 0);
    zero_all<<<(NN * 16 + NN / 4 + 255) / 256, 256, 0, s2>>>(
        (float4*)out, (const unsigned*)src);
    cudaEventRecord(evZero, s2);
    hist_kernel<<<(EE + 255) / 256, 256, 0, s2>>>(dst);
    scan_kernel<<<1, 1024, 0, s2>>>();
    scatter_kernel<<<(EE + 255) / 256, 256, 0, s2>>>(src, dst);
    cudaEventRecord(evCSR, s2);

    // Fork s3: resval after zero (RED into out, concurrent with gather).
    cudaStreamWaitEvent(s3, evZero, 0);
    resval_kernel<<<node_blocks, 128, resval_smem, s3>>>(h, Wres, out);
    cudaEventRecord(evResv, s3);

    // Main stream: feat, then gather (needs feat + CSR + zeroed out).
    feat_kernel<<<node_blocks, 128, feat_smem>>>(h, Wfc, al, ar);
    cudaStreamWaitEvent(0, evCSR, 0);
    gather_kernel<<<(NN * 32 + 255) / 256, 256>>>(out);

    // Join resval.
    cudaStreamWaitEvent(0, evResv, 0);
}

// round 16
// speedup vs baseline: 1.9011x; 1.9011x over previous
#include <cuda_runtime.h>
#include <cuda_fp16.h>
#include <cstdint>

#define NN 50000
#define EE 800000
#define NPB 128   // nodes per block (resval kernel)
#define FNB 256   // nodes per block (feat kernel)
#define HS_H 72   // h-tile smem stride in halves (144 B)
#define WT_S 72   // transposed-W smem stride in halves

// Scratch (allocation-free rule: __device__ globals)
__device__ __half g_feat[NN * 64];   // fp16 feat: 128 B / node record
__device__ float  g_el[NN * 4];
__device__ float  g_er[NN * 4];
__device__ int    g_idx64;           // 1 if src/dst are int64, 0 if int32

__device__ __forceinline__ uint32_t smem_u32(const void* p)
{
    return (uint32_t)__cvta_generic_to_shared(p);
}

// ---------------------------------------------------------------------------
// Zero kernel: out = 0 (out is poisoned; resval and edge RED-add onto it).
// Also probes index dtype (node ids < 2^31 => int64 encoding has zero high
// words at odd 32-bit slots).
// ---------------------------------------------------------------------------
__global__ __launch_bounds__(256)
void zero_kernel(float4* __restrict__ out4, const unsigned* __restrict__ src_words)
{
    const int i = blockIdx.x * 256 + threadIdx.x;
    if (i == 0) {
        g_idx64 = (src_words[1] == 0u && src_words[3] == 0u &&
                   src_words[5] == 0u && src_words[7] == 0u) ? 1 : 0;
    }
    if (i < NN * 16) out4[i] = make_float4(0.f, 0.f, 0.f, 0.f);
}

// ---------------------------------------------------------------------------
// feat kernel (fp16 tensor cores, ldmatrix-fed): feat = h@W_fc (stored fp16),
// el/er head-dots from the fp32 accumulators.
// 256 threads = 8 warps; warp w owns rows w*32..w*32+31 x all 64 cols as
// 2 (M16) x 8 (N8) m16n8k16 tiles, K=64 in 4 steps. 256 nodes per block
// (196 blocks) to amortize W staging and block overheads.
// ---------------------------------------------------------------------------
__global__ __launch_bounds__(256)
void feat_kernel(const float* __restrict__ h,
                 const float* __restrict__ Wfc,
                 const float* __restrict__ al,
                 const float* __restrict__ ar)
{
    extern __shared__ float smem[];
    __half* hs   = reinterpret_cast<__half*>(smem);           // [256][HS_H]
    __half* Wt   = hs + FNB * HS_H;                           // [64][WT_S]
    float*  al_s = reinterpret_cast<float*>(Wt + 64 * WT_S);  // 64
    float*  ar_s = al_s + 64;                                 // 64

    const int t   = threadIdx.x;
    const int nb0 = blockIdx.x * FNB;

    if (t < 64)       al_s[t]      = al[t];
    else if (t < 128) ar_s[t - 64] = ar[t - 64];

    // Stage W transposed as fp16: Wt[n][k] = W[k][n]  (4096 elems / 256 thr)
    #pragma unroll
    for (int i = 0; i < 16; i++) {
        const int idx = i * 256 + t;
        const int k = idx >> 6, n = idx & 63;
        Wt[n * WT_S + k] = __float2half(Wfc[idx]);
    }

    // Stage h row t as fp16
    {
        const int n = nb0 + t;
        #pragma unroll
        for (int k4 = 0; k4 < 16; k4++) {
            float4 v = make_float4(0.f, 0.f, 0.f, 0.f);
            if (n < NN) v = reinterpret_cast<const float4*>(h)[n * 16 + k4];
            *reinterpret_cast<__half2*>(&hs[t * HS_H + k4 * 4 + 0]) =
                __floats2half2_rn(v.x, v.y);
            *reinterpret_cast<__half2*>(&hs[t * HS_H + k4 * 4 + 2]) =
                __floats2half2_rn(v.z, v.w);
        }
    }
    __syncthreads();

    const int w   = t >> 5;          // 0..7
    const int ln  = t & 31;
    const int gid = ln >> 2;
    const int q   = ln & 3;
    const int rbase = w * 32;

    const int arow_l = ln & 15;
    const int akoff  = (ln >> 4) * 8;
    const int brow_l = ln & 7;
    const int bj     = ln >> 3;
    const int bkoff  = (bj & 1) * 8;
    const int bnsel  = bj >> 1;

    const uint32_t hs_base = smem_u32(hs);
    const uint32_t wt_base = smem_u32(Wt);

    float acc[2][8][4];
    #pragma unroll
    for (int m = 0; m < 2; m++)
        #pragma unroll
        for (int nt = 0; nt < 8; nt++)
            #pragma unroll
            for (int c = 0; c < 4; c++) acc[m][nt][c] = 0.f;

    #pragma unroll
    for (int ks = 0; ks < 4; ks++) {
        const int k0 = ks * 16;
        uint32_t a[2][4];
        #pragma unroll
        for (int m = 0; m < 2; m++) {
            const uint32_t addr = hs_base +
                ((rbase + m * 16 + arow_l) * HS_H + k0 + akoff) * 2;
            asm volatile(
                "ldmatrix.sync.aligned.m8n8.x4.shared.b16 {%0,%1,%2,%3}, [%4];"
                : "=r"(a[m][0]), "=r"(a[m][1]), "=r"(a[m][2]), "=r"(a[m][3])
                : "r"(addr));
        }
        #pragma unroll
        for (int np = 0; np < 4; np++) {
            uint32_t b[4];
            const int nrow = (2 * np + bnsel) * 8 + brow_l;
            const uint32_t baddr = wt_base + (nrow * WT_S + k0 + bkoff) * 2;
            asm volatile(
                "ldmatrix.sync.aligned.m8n8.x4.shared.b16 {%0,%1,%2,%3}, [%4];"
                : "=r"(b[0]), "=r"(b[1]), "=r"(b[2]), "=r"(b[3])
                : "r"(baddr));
            #pragma unroll
            for (int hf = 0; hf < 2; hf++) {
                const int nt = 2 * np + hf;
                #pragma unroll
                for (int m = 0; m < 2; m++) {
                    asm volatile(
                        "mma.sync.aligned.m16n8k16.row.col.f32.f16.f16.f32 "
                        "{%0,%1,%2,%3},{%4,%5,%6,%7},{%8,%9},{%0,%1,%2,%3};"
                        : "+f"(acc[m][nt][0]), "+f"(acc[m][nt][1]),
                          "+f"(acc[m][nt][2]), "+f"(acc[m][nt][3])
                        : "r"(a[m][0]), "r"(a[m][1]), "r"(a[m][2]), "r"(a[m][3]),
                          "r"(b[hf * 2 + 0]), "r"(b[hf * 2 + 1]));
                }
            }
        }
    }

    // Epilogue: per lane rows (m, gid + 8*half); cols nt*8 + 2q, +1.
    #pragma unroll
    for (int m = 0; m < 2; m++) {
        #pragma unroll
        for (int half = 0; half < 2; half++) {
            const int n = nb0 + rbase + m * 16 + gid + half * 8;
            float e_l[4] = {0.f, 0.f, 0.f, 0.f};
            float e_r[4] = {0.f, 0.f, 0.f, 0.f};
            #pragma unroll
            for (int nt = 0; nt < 8; nt++) {
                const int hH  = nt >> 1;
                const int c16 = (nt & 1) * 8 + 2 * q;
                const float v0 = acc[m][nt][half * 2 + 0];
                const float v1 = acc[m][nt][half * 2 + 1];
                e_l[hH] += v0 * al_s[hH * 16 + c16] + v1 * al_s[hH * 16 + c16 + 1];
                e_r[hH] += v0 * ar_s[hH * 16 + c16] + v1 * ar_s[hH * 16 + c16 + 1];
            }
            #pragma unroll
            for (int hH = 0; hH < 4; hH++) {
                e_l[hH] += __shfl_xor_sync(0xFFFFFFFFu, e_l[hH], 1);
                e_l[hH] += __shfl_xor_sync(0xFFFFFFFFu, e_l[hH], 2);
                e_r[hH] += __shfl_xor_sync(0xFFFFFFFFu, e_r[hH], 1);
                e_r[hH] += __shfl_xor_sync(0xFFFFFFFFu, e_r[hH], 2);
            }
            if (n < NN) {
                #pragma unroll
                for (int nt = 0; nt < 8; nt++) {
                    const __half2 hv = __floats2half2_rn(acc[m][nt][half * 2 + 0],
                                                         acc[m][nt][half * 2 + 1]);
                    *reinterpret_cast<__half2*>(&g_feat[n * 64 + nt * 8 + 2 * q]) = hv;
                }
                const float ev = (q == 0) ? e_l[0] : (q == 1) ? e_l[1]
                               : (q == 2) ? e_l[2] : e_l[3];
                const float rv = (q == 0) ? e_r[0] : (q == 1) ? e_r[1]
                               : (q == 2) ? e_r[2] : e_r[3];
                g_el[n * 4 + q] = ev;
                g_er[n * 4 + q] = rv;
            }
        }
    }
}

// ---------------------------------------------------------------------------
// resval kernel (fp32 FFMA, off critical path): out += h @ W_res via RED,
// concurrent with edge_kernel's RED accumulation (addition commutes).
// ---------------------------------------------------------------------------
__global__ __launch_bounds__(128, 4)
void resval_kernel(const float* __restrict__ h,
                   const float* __restrict__ Wres,
                   float* __restrict__ out)
{
    extern __shared__ float smem[];
    float* sW = smem;
    float* sT = smem + 4096;

    const int t   = threadIdx.x;
    const int nb0 = blockIdx.x * NPB;

    #pragma unroll
    for (int i = 0; i < 32; i++) sW[i * 128 + t] = Wres[i * 128 + t];

    {
        const int n = nb0 + t;
        #pragma unroll
        for (int k4 = 0; k4 < 16; k4++) {
            float4 v = make_float4(0.f, 0.f, 0.f, 0.f);
            if (n < NN) v = reinterpret_cast<const float4*>(h)[n * 16 + k4];
            sT[(k4 * 4 + 0) * 128 + t] = v.x;
            sT[(k4 * 4 + 1) * 128 + t] = v.y;
            sT[(k4 * 4 + 2) * 128 + t] = v.z;
            sT[(k4 * 4 + 3) * 128 + t] = v.w;
        }
    }
    __syncthreads();

    const int g    = t >> 2;
    const int head = t & 3;

    const float4* sT4 = reinterpret_cast<const float4*>(sT);
    const float4* sW4 = reinterpret_cast<const float4*>(sW);

    float acc[4][16];
    #pragma unroll
    for (int i = 0; i < 4; i++)
        #pragma unroll
        for (int j = 0; j < 16; j++) acc[i][j] = 0.f;

    #pragma unroll 4
    for (int k = 0; k < 64; k++) {
        float4 hv = sT4[k * 32 + g];
        float hvv[4] = {hv.x, hv.y, hv.z, hv.w};
        #pragma unroll
        for (int jq = 0; jq < 4; jq++) {
            float4 wv = sW4[k * 16 + head * 4 + jq];
            #pragma unroll
            for (int i = 0; i < 4; i++) {
                acc[i][jq * 4 + 0] += hvv[i] * wv.x;
                acc[i][jq * 4 + 1] += hvv[i] * wv.y;
                acc[i][jq * 4 + 2] += hvv[i] * wv.z;
                acc[i][jq * 4 + 3] += hvv[i] * wv.w;
            }
        }
    }

    #pragma unroll
    for (int i = 0; i < 4; i++) {
        const int n = nb0 + g * 4 + i;
        if (n < NN) {
            float* op = &out[n * 64 + head * 16];
            #pragma unroll
            for (int jq = 0; jq < 4; jq++) {
                asm volatile("red.global.add.v4.f32 [%0], {%1,%2,%3,%4};"
                             :: "l"(op + jq * 4),
                                "f"(acc[i][jq * 4 + 0]), "f"(acc[i][jq * 4 + 1]),
                                "f"(acc[i][jq * 4 + 2]), "f"(acc[i][jq * 4 + 3])
                             : "memory");
            }
        }
    }
}

// ---------------------------------------------------------------------------
// Edge kernel (the proven 55.8 us flat version): 4 threads (one quad) per
// edge. Head-softmax via quad shuffles. fp16 feat gather (quad covers one
// 32 B sector per step); fp32 vector RED scatter (contiguous 64 B per step).
// At the L1-wavefront floor; 3.2M lanes give maximal latency parallelism.
// ---------------------------------------------------------------------------
__global__ __launch_bounds__(256)
void edge_kernel(const void* __restrict__ src_raw,
                 const void* __restrict__ dst_raw,
                 float* __restrict__ out)
{
    const int t = blockIdx.x * 256 + threadIdx.x;
    const int e = t >> 2;
    if (e >= EE) return;
    const int q    = t & 3;
    const int lane = threadIdx.x & 31;

    int s, d;
    if (g_idx64) {
        s = (int)__ldg(&((const long long*)src_raw)[e]);
        d = (int)__ldg(&((const long long*)dst_raw)[e]);
    } else {
        s = __ldg(&((const int*)src_raw)[e]);
        d = __ldg(&((const int*)dst_raw)[e]);
    }

    float x = __ldg(&g_el[s * 4 + q]) + __ldg(&g_er[d * 4 + q]);
    x = (x > 0.f) ? x : 0.2f * x;                       // leaky relu

    float m = x;
    m = fmaxf(m, __shfl_xor_sync(0xFFFFFFFFu, m, 1));
    m = fmaxf(m, __shfl_xor_sync(0xFFFFFFFFu, m, 2));
    const float p = __expf(x - m);
    float ssum = p;
    ssum += __shfl_xor_sync(0xFFFFFFFFu, ssum, 1);
    ssum += __shfl_xor_sync(0xFFFFFFFFu, ssum, 2);
    const float a = p / ssum;

    const uint2* fh = reinterpret_cast<const uint2*>(g_feat + s * 64);
    float*       o  = out + d * 64;
    const int    qb = lane & ~3;

    #pragma unroll
    for (int j = 0; j < 4; j++) {
        const float aj = __shfl_sync(0xFFFFFFFFu, a, qb + j);
        const int   c  = j * 4 + q;
        const uint2 u  = __ldg(&fh[c]);
        const __half2 h0 = *reinterpret_cast<const __half2*>(&u.x);
        const __half2 h1 = *reinterpret_cast<const __half2*>(&u.y);
        const float2 f0 = __half22float2(h0);
        const float2 f1 = __half22float2(h1);
        asm volatile("red.global.add.v4.f32 [%0], {%1,%2,%3,%4};"
                     :: "l"(o + c * 4),
                        "f"(f0.x * aj), "f"(f0.y * aj), "f"(f1.x * aj), "f"(f1.y * aj)
                     : "memory");
    }
}

// ---------------------------------------------------------------------------
// Schedule (R10 structure):
//   s2 : zero(out,probe) ──► resval (RED into out) ───────[evJoin]
//   s1 : feat(mma,256) ──► [wait evZero] edge ─────────► [wait evJoin]
// ---------------------------------------------------------------------------
extern "C" void kernel_launch(void* const* d_in, const int* in_sizes, int n_in,
                              void* d_out, int out_size)
{
    const float* h    = (const float*)d_in[0];
    const void*  src  = d_in[1];
    const void*  dst  = d_in[2];
    const float* Wfc  = (const float*)d_in[3];
    const float* al   = (const float*)d_in[4];
    const float* ar   = (const float*)d_in[5];
    const float* Wres = (const float*)d_in[6];
    float* out = (float*)d_out;

    const int feat_smem   = (FNB * HS_H + 64 * WT_S) * 2 + 128 * (int)sizeof(float);
    const int resval_smem = (4096 + 64 * NPB) * (int)sizeof(float);

    // One-time host-side resources (no device memory involved).
    static bool         s_init = false;
    static cudaStream_t s2;
    static cudaEvent_t  evFork, evZero, evJoin;
    if (!s_init) {
        cudaStreamCreateWithFlags(&s2, cudaStreamNonBlocking);
        cudaEventCreateWithFlags(&evFork, cudaEventDisableTiming);
        cudaEventCreateWithFlags(&evZero, cudaEventDisableTiming);
        cudaEventCreateWithFlags(&evJoin, cudaEventDisableTiming);
        cudaFuncSetAttribute(feat_kernel,
                             cudaFuncAttributeMaxDynamicSharedMemorySize, feat_smem);
        cudaFuncSetAttribute(resval_kernel,
                             cudaFuncAttributeMaxDynamicSharedMemorySize, resval_smem);
        s_init = true;
    }

    // Fork s2: zero out, then resval RED-adds into it.
    cudaEventRecord(evFork, 0);
    cudaStreamWaitEvent(s2, evFork, 0);
    zero_kernel<<<(NN * 16 + 255) / 256, 256, 0, s2>>>((float4*)out,
                                                       (const unsigned*)src);
    cudaEventRecord(evZero, s2);
    resval_kernel<<<(NN + NPB - 1) / NPB, 128, resval_smem, s2>>>(h, Wres, out);
    cudaEventRecord(evJoin, s2);

    // Main stream: feat, then edge (edge needs feat AND zeroed out).
    feat_kernel<<<(NN + FNB - 1) / FNB, 256, feat_smem>>>(h, Wfc, al, ar);
    cudaStreamWaitEvent(0, evZero, 0);

    const int edge_blocks = (EE * 4) / 256;          // 12500 (exact)
    edge_kernel<<<edge_blocks, 256>>>(src, dst, out);

    // Join: resval must also be complete before the result is read.
    cudaStreamWaitEvent(0, evJoin, 0);
}